// round 17
// baseline (speedup 1.0000x reference)
#include <cuda_runtime.h>
#include <cuda_fp16.h>
#include <mma.h>
#include <cstdint>

using namespace nvcuda;

// Problem constants (fixed-shape problem)
constexpr int NN   = 10000;         // nodes
constexpr int F    = 256;           // feature dim
constexpr int NF   = NN * F;        // elems per matrix
constexpr int EMAX = 320000;        // edges
constexpr int WSZ  = 65536;         // 256*256 per W
constexpr int SCAN_BLK = 1024;

// Scratch (__device__ globals; no allocation allowed)
__device__ __half g_h[3 * NF];      // H1|H2|H3 = fp16(X@W1..3)
__device__ __half g_s[2 * NF];      // s1, s2 intermediates (fp16)
__device__ __half g_xh[NF];         // fp16 X
__device__ __half g_wh[3 * WSZ];    // fp16 W1|W2|W3
__device__ int    g_cnt[NN];
__device__ int    g_rowptr[NN + 1];
__device__ int    g_off[NN];
__device__ int2   g_epack[EMAX];    // CSR-ordered (src, __float_as_int(val))

// ---------------------------------------------------------------------------
// fp16 helpers
// ---------------------------------------------------------------------------
__device__ __forceinline__ float2 h2f(unsigned u) {
    __half2 h = *reinterpret_cast<__half2*>(&u);
    return __half22float2(h);
}
__device__ __forceinline__ unsigned f2h(float a, float b) {
    __half2 h = __floats2half2_rn(a, b);
    return *reinterpret_cast<unsigned*>(&h);
}

// ---------------------------------------------------------------------------
// Fused fp32->fp16 convert: X and W1..W3 in one launch (index-partitioned)
// ---------------------------------------------------------------------------
__global__ void conv_all_kernel(const float4* __restrict__ x,
                                const float4* __restrict__ W1,
                                const float4* __restrict__ W2,
                                const float4* __restrict__ W3,
                                uint2* __restrict__ xh, uint2* __restrict__ wh,
                                int n_x4)
{
    const int n_w4 = WSZ / 4;
    const int total = n_x4 + 3 * n_w4;
    int i = blockIdx.x * blockDim.x + threadIdx.x;
    int stride = gridDim.x * blockDim.x;
    for (; i < total; i += stride) {
        float4 v;
        uint2* out;
        if (i < n_x4) {
            v = __ldg(x + i);
            out = xh + i;
        } else {
            int j = i - n_x4;
            int which = j / n_w4;
            int k = j - which * n_w4;
            const float4* Wp = (which == 0) ? W1 : (which == 1) ? W2 : W3;
            v = __ldg(Wp + k);
            out = wh + (size_t)which * (WSZ / 4) + k;
        }
        uint2 o;
        o.x = f2h(v.x, v.y);
        o.y = f2h(v.z, v.w);
        *out = o;
    }
}

// ---------------------------------------------------------------------------
// CSR build: memset(cnt) -> histogram -> fused scan (read-only) -> scatter
// All edge-array loads vectorized int4/float4 (E % 4 == 0 fast path).
// ---------------------------------------------------------------------------
__global__ void hist_kernel(const int* __restrict__ dst, int* cnt, int E) {
    int i = blockIdx.x * blockDim.x + threadIdx.x;     // one int4 per thread
    int i0 = i * 4;
    if (i0 + 3 < E) {
        int4 d = __ldg(reinterpret_cast<const int4*>(dst) + i);
        atomicAdd(&cnt[d.x], 1);
        atomicAdd(&cnt[d.y], 1);
        atomicAdd(&cnt[d.z], 1);
        atomicAdd(&cnt[d.w], 1);
    } else {
        for (int j = i0; j < E; j++) atomicAdd(&cnt[__ldg(dst + j)], 1);
    }
}

// Fused scan: each block b computes its prefix by cooperatively summing
// cnt[0 .. b*1024) with 4 independent accumulators (breaks the dependent-load
// chain), then does a block-local shuffle scan of its own 1024 elements.
// STRICTLY READ-ONLY on cnt (cross-block reads — R15's self-zero raced here).
__global__ __launch_bounds__(SCAN_BLK) void scan_kernel(
    const int* __restrict__ cnt, int* rowptr, int* off, int n)
{
    int tid = threadIdx.x;
    int b   = blockIdx.x;
    int idx = b * SCAN_BLK + tid;
    int lane = tid & 31, w = tid >> 5;
    __shared__ int ws[32];
    __shared__ int blockpre_s;

    // --- cross-block prefix: reduce cnt[0 .. b*1024), MLP=4 ---
    const int lim = b * SCAN_BLK;
    int p0 = 0, p1 = 0, p2 = 0, p3 = 0;
    int i = tid;
    for (; i + 3 * SCAN_BLK < lim; i += 4 * SCAN_BLK) {
        p0 += __ldg(cnt + i);
        p1 += __ldg(cnt + i + SCAN_BLK);
        p2 += __ldg(cnt + i + 2 * SCAN_BLK);
        p3 += __ldg(cnt + i + 3 * SCAN_BLK);
    }
    for (; i < lim; i += SCAN_BLK) p0 += __ldg(cnt + i);
    int pre = (p0 + p1) + (p2 + p3);
#pragma unroll
    for (int d = 16; d > 0; d >>= 1)
        pre += __shfl_down_sync(0xFFFFFFFFu, pre, d);
    if (lane == 0) ws[w] = pre;
    __syncthreads();
    if (tid == 0) {
        int t = 0;
#pragma unroll
        for (int k = 0; k < 32; k++) t += ws[k];
        blockpre_s = t;
    }
    __syncthreads();
    int blockpre = blockpre_s;
    __syncthreads();   // ws reused below

    // --- block-local scan of own 1024 elements ---
    int v = (idx < n) ? __ldg(cnt + idx) : 0;
    int cs = v;
#pragma unroll
    for (int d = 1; d < 32; d <<= 1) {
        int t = __shfl_up_sync(0xFFFFFFFFu, cs, d);
        if (lane >= d) cs += t;
    }
    if (lane == 31) ws[w] = cs;
    __syncthreads();
    if (w == 0) {
        int t = ws[lane];
#pragma unroll
        for (int d = 1; d < 32; d <<= 1) {
            int u = __shfl_up_sync(0xFFFFFFFFu, t, d);
            if (lane >= d) t += u;
        }
        ws[lane] = t;
    }
    __syncthreads();
    int warppre = (w == 0) ? 0 : ws[w - 1];
    int excl = blockpre + warppre + cs - v;

    if (idx < n) {
        off[idx] = excl;
        rowptr[idx + 1] = excl + v;
    }
    if (idx == 0) rowptr[0] = 0;
}

__global__ void scatter_kernel(const int* __restrict__ src, const int* __restrict__ dst,
                               const float* __restrict__ vals,
                               int* off, int2* epack, int E) {
    int i = blockIdx.x * blockDim.x + threadIdx.x;     // one int4 group per thread
    int i0 = i * 4;
    if (i0 + 3 < E) {
        int4   d = __ldg(reinterpret_cast<const int4*>(dst) + i);
        int4   s = __ldg(reinterpret_cast<const int4*>(src) + i);
        float4 v = __ldg(reinterpret_cast<const float4*>(vals) + i);
        int p0 = atomicAdd(&off[d.x], 1);
        int p1 = atomicAdd(&off[d.y], 1);
        int p2 = atomicAdd(&off[d.z], 1);
        int p3 = atomicAdd(&off[d.w], 1);
        epack[p0] = make_int2(s.x, __float_as_int(v.x));
        epack[p1] = make_int2(s.y, __float_as_int(v.y));
        epack[p2] = make_int2(s.z, __float_as_int(v.z));
        epack[p3] = make_int2(s.w, __float_as_int(v.w));
    } else {
        for (int j = i0; j < E; j++) {
            int p = atomicAdd(&off[__ldg(dst + j)], 1);
            epack[p] = make_int2(__ldg(src + j), __float_as_int(__ldg(vals + j)));
        }
    }
}

// ---------------------------------------------------------------------------
// Tensor-core GEMM (fp16-staged, synchronous — R12 version, known-good):
// H = fp16( Xh @ [W1|W2|W3]h ). wmma m16n16k16, fp32 acc.
// Block 256 = 8 warps (4m x 2n). Tile BM=128, BN=128, BK=64.
// Grid: (6, ceil(M/128)).
// ---------------------------------------------------------------------------
constexpr int GBM = 128;
constexpr int GBN = 128;
constexpr int GBK = 64;
constexpr int APADH = 72;    // half-stride for As (144B)
constexpr int BPADH = 136;   // half-stride for Bs (272B)

__global__ __launch_bounds__(256) void gemm_wmma(
    const __half* __restrict__ xh,
    const __half* __restrict__ wh,
    __half* __restrict__ H, int M)
{
    __shared__ alignas(16) __half As[GBM][APADH];
    __shared__ alignas(16) __half Bs[GBK][BPADH];

    const int n0 = blockIdx.x * GBN;       // over concat width 768
    const int m0 = blockIdx.y * GBM;
    const int which = n0 >> 8;
    const int wc0 = n0 & 255;
    const __half* Wp = wh + (size_t)which * WSZ;

    const int tid = threadIdx.x;
    const int wid = tid >> 5;
    const int warp_m = wid >> 1;           // 0..3 -> 32 rows each
    const int warp_n = wid & 1;            // 0..1 -> 64 cols each

    wmma::fragment<wmma::accumulator, 16, 16, 16, float> cf[2][4];
#pragma unroll
    for (int i = 0; i < 2; i++)
#pragma unroll
        for (int j = 0; j < 4; j++) wmma::fill_fragment(cf[i][j], 0.f);

    for (int k0 = 0; k0 < 256; k0 += GBK) {
        // A tile: 128 rows x 64 halfs = 1024 uint4, 4 per thread
#pragma unroll
        for (int l = 0; l < 4; l++) {
            int s   = tid + l * 256;       // 0..1023
            int row = s >> 3;              // 0..127
            int c4  = s & 7;               // uint4 col (8 halfs)
            int gm  = m0 + row;
            uint4 v = make_uint4(0u, 0u, 0u, 0u);
            if (gm < M)
                v = *reinterpret_cast<const uint4*>(xh + (size_t)gm * 256 + k0 + c4 * 8);
            *reinterpret_cast<uint4*>(&As[row][c4 * 8]) = v;
        }
        // B tile: 64 k-rows x 128 halfs = 1024 uint4
#pragma unroll
        for (int l = 0; l < 4; l++) {
            int s  = tid + l * 256;
            int kr = s >> 4;               // 0..63
            int c4 = s & 15;               // uint4 col
            uint4 v = *reinterpret_cast<const uint4*>(
                Wp + (size_t)(k0 + kr) * 256 + wc0 + c4 * 8);
            *reinterpret_cast<uint4*>(&Bs[kr][c4 * 8]) = v;
        }
        __syncthreads();

#pragma unroll
        for (int kk = 0; kk < GBK; kk += 16) {
            wmma::fragment<wmma::matrix_a, 16, 16, 16, __half, wmma::row_major> af[2];
            wmma::fragment<wmma::matrix_b, 16, 16, 16, __half, wmma::row_major> bf[4];
#pragma unroll
            for (int mi = 0; mi < 2; mi++)
                wmma::load_matrix_sync(af[mi], &As[warp_m * 32 + mi * 16][kk], APADH);
#pragma unroll
            for (int ni = 0; ni < 4; ni++)
                wmma::load_matrix_sync(bf[ni], &Bs[kk][warp_n * 64 + ni * 16], BPADH);
#pragma unroll
            for (int mi = 0; mi < 2; mi++)
#pragma unroll
                for (int ni = 0; ni < 4; ni++)
                    wmma::mma_sync(cf[mi][ni], af[mi], bf[ni], cf[mi][ni]);
        }
        __syncthreads();
    }

    __half* Hout = H + (size_t)which * NF;
#pragma unroll
    for (int mi = 0; mi < 2; mi++) {
        int gm = m0 + warp_m * 32 + mi * 16;
        if (gm < M) {   // M % 16 == 0 -> whole fragment valid or out
#pragma unroll
            for (int ni = 0; ni < 4; ni++) {
                wmma::fragment<wmma::accumulator, 16, 16, 16, __half> ch;
#pragma unroll
                for (int e = 0; e < ch.num_elements; e++)
                    ch.x[e] = __float2half(cf[mi][ni].x[e]);
                wmma::store_matrix_sync(
                    Hout + (size_t)gm * 256 + wc0 + warp_n * 64 + ni * 16,
                    ch, 256, wmma::mem_row_major);
            }
        }
    }
}

// ---------------------------------------------------------------------------
// Horner SpMM pass: r = A @ gin (+ addin[row]); store fp16 (or relu(r/3) fp32).
// Warp per destination row. Lane owns halfs [8*lane, 8*lane+8) = one uint4.
// 4-edge batching (MLP=4 on the 512B row gathers). Packed int2 edge records.
// ---------------------------------------------------------------------------
__device__ __forceinline__ void acc_row(float* acc, uint4 r, float v) {
    float2 f0 = h2f(r.x), f1 = h2f(r.y), f2 = h2f(r.z), f3 = h2f(r.w);
    acc[0] = fmaf(v, f0.x, acc[0]); acc[1] = fmaf(v, f0.y, acc[1]);
    acc[2] = fmaf(v, f1.x, acc[2]); acc[3] = fmaf(v, f1.y, acc[3]);
    acc[4] = fmaf(v, f2.x, acc[4]); acc[5] = fmaf(v, f2.y, acc[5]);
    acc[6] = fmaf(v, f3.x, acc[6]); acc[7] = fmaf(v, f3.y, acc[7]);
}

template <bool ADD, bool FINAL>
__global__ __launch_bounds__(256) void spmm_pass(
    const int* __restrict__ rowptr, const int2* __restrict__ epack,
    const __half* __restrict__ gin,
    const __half* __restrict__ addin,
    __half* __restrict__ hout,
    float* __restrict__ fout, int n)
{
    int row = blockIdx.x * 8 + (threadIdx.x >> 5);
    if (row >= n) return;
    int lane = threadIdx.x & 31;
    int beg = rowptr[row], end = rowptr[row + 1];

    const uint4* base = reinterpret_cast<const uint4*>(gin);   // 32 uint4 per row

    float acc[8] = {0, 0, 0, 0, 0, 0, 0, 0};

    int e = beg;
    for (; e + 3 < end; e += 4) {
        int2 p0 = __ldg(epack + e),     p1 = __ldg(epack + e + 1);
        int2 p2 = __ldg(epack + e + 2), p3 = __ldg(epack + e + 3);
        uint4 r0 = __ldg(base + (size_t)p0.x * 32 + lane);
        uint4 r1 = __ldg(base + (size_t)p1.x * 32 + lane);
        uint4 r2 = __ldg(base + (size_t)p2.x * 32 + lane);
        uint4 r3 = __ldg(base + (size_t)p3.x * 32 + lane);
        acc_row(acc, r0, __int_as_float(p0.y));
        acc_row(acc, r1, __int_as_float(p1.y));
        acc_row(acc, r2, __int_as_float(p2.y));
        acc_row(acc, r3, __int_as_float(p3.y));
    }
    for (; e < end; e++) {
        int2 p = __ldg(epack + e);
        uint4 r = __ldg(base + (size_t)p.x * 32 + lane);
        acc_row(acc, r, __int_as_float(p.y));
    }

    if (ADD) {
        uint4 q = __ldg(reinterpret_cast<const uint4*>(addin) + (size_t)row * 32 + lane);
        float2 f0 = h2f(q.x), f1 = h2f(q.y), f2 = h2f(q.z), f3 = h2f(q.w);
        acc[0] += f0.x; acc[1] += f0.y; acc[2] += f1.x; acc[3] += f1.y;
        acc[4] += f2.x; acc[5] += f2.y; acc[6] += f3.x; acc[7] += f3.y;
    }

    if (FINAL) {
        const float inv3 = 1.0f / 3.0f;
        float4 r0, r1;
        r0.x = fmaxf(acc[0], 0.f) * inv3; r0.y = fmaxf(acc[1], 0.f) * inv3;
        r0.z = fmaxf(acc[2], 0.f) * inv3; r0.w = fmaxf(acc[3], 0.f) * inv3;
        r1.x = fmaxf(acc[4], 0.f) * inv3; r1.y = fmaxf(acc[5], 0.f) * inv3;
        r1.z = fmaxf(acc[6], 0.f) * inv3; r1.w = fmaxf(acc[7], 0.f) * inv3;
        float4* op = reinterpret_cast<float4*>(fout + (size_t)row * 256 + lane * 8);
        op[0] = r0; op[1] = r1;
    } else {
        uint4 o;
        o.x = f2h(acc[0], acc[1]);
        o.y = f2h(acc[2], acc[3]);
        o.z = f2h(acc[4], acc[5]);
        o.w = f2h(acc[6], acc[7]);
        *(reinterpret_cast<uint4*>(hout) + (size_t)row * 32 + lane) = o;
    }
}

// ---------------------------------------------------------------------------
// Launch — fork/join: (convert + GEMM) on side stream || CSR build on main.
// ---------------------------------------------------------------------------
static cudaStream_t g_s2 = nullptr;
static cudaEvent_t  g_evFork = nullptr, g_evJoin = nullptr;

extern "C" void kernel_launch(void* const* d_in, const int* in_sizes, int n_in,
                              void* d_out, int out_size)
{
    const float* x    = (const float*)d_in[0];
    const float* vals = (const float*)d_in[1];
    const float* W1   = (const float*)d_in[2];
    const float* W2   = (const float*)d_in[3];
    const float* W3   = (const float*)d_in[4];
    const int*   src  = (const int*)d_in[5];
    const int*   dst  = (const int*)d_in[6];

    const int M = in_sizes[0] / F;   // nodes
    const int E = in_sizes[1];       // edges

    __half* h;     cudaGetSymbolAddress((void**)&h,      g_h);
    __half* sbuf;  cudaGetSymbolAddress((void**)&sbuf,   g_s);
    __half* xh;    cudaGetSymbolAddress((void**)&xh,     g_xh);
    __half* wh;    cudaGetSymbolAddress((void**)&wh,     g_wh);
    int*   cnt;    cudaGetSymbolAddress((void**)&cnt,    g_cnt);
    int*   rowptr; cudaGetSymbolAddress((void**)&rowptr, g_rowptr);
    int*   off;    cudaGetSymbolAddress((void**)&off,    g_off);
    int2*  epack;  cudaGetSymbolAddress((void**)&epack,  g_epack);

    __half* h1 = h;
    __half* h2 = h + (size_t)NF;
    __half* h3 = h + (size_t)2 * NF;
    __half* s1 = sbuf;
    __half* s2 = sbuf + (size_t)NF;

    if (!g_s2) {
        cudaStreamCreateWithFlags(&g_s2, cudaStreamNonBlocking);
        cudaEventCreateWithFlags(&g_evFork, cudaEventDisableTiming);
        cudaEventCreateWithFlags(&g_evJoin, cudaEventDisableTiming);
    }

    // --- fork: convert + GEMM on side stream ---
    cudaEventRecord(g_evFork, 0);
    cudaStreamWaitEvent(g_s2, g_evFork, 0);
    conv_all_kernel<<<1024, 256, 0, g_s2>>>(
        (const float4*)x, (const float4*)W1, (const float4*)W2, (const float4*)W3,
        (uint2*)xh, (uint2*)wh, M * F / 4);
    {
        dim3 grid(768 / GBN, (M + GBM - 1) / GBM);
        gemm_wmma<<<grid, 256, 0, g_s2>>>(xh, wh, h, M);
    }

    // --- CSR build on main stream (concurrent with GEMM) ---
    cudaMemsetAsync(cnt, 0, (size_t)M * sizeof(int), 0);
    hist_kernel<<<(E / 4 + 255) / 256, 256>>>(dst, cnt, E);
    {
        int nblk = (M + SCAN_BLK - 1) / SCAN_BLK;
        scan_kernel<<<nblk, SCAN_BLK>>>(cnt, rowptr, off, M);
    }
    scatter_kernel<<<(E / 4 + 255) / 256, 256>>>(src, dst, vals, off, epack, E);

    // --- join ---
    cudaEventRecord(g_evJoin, g_s2);
    cudaStreamWaitEvent(0, g_evJoin, 0);

    // --- Horner SpMM chain: out = relu( A@(h1 + A@(h2 + A@h3)) / 3 ) ---
    const int rows_blocks = (M + 7) / 8;
    // s1 = A@h3 + h2
    spmm_pass<true, false><<<rows_blocks, 256>>>(rowptr, epack, h3, h2, s1, nullptr, M);
    // s2 = A@s1 + h1
    spmm_pass<true, false><<<rows_blocks, 256>>>(rowptr, epack, s1, h1, s2, nullptr, M);
    // out = relu(A@s2 / 3)
    spmm_pass<false, true><<<rows_blocks, 256>>>(rowptr, epack, s2, nullptr, nullptr,
                                                 (float*)d_out, M);
}